// round 2
// baseline (speedup 1.0000x reference)
#include <cuda_runtime.h>
#include <math.h>

#define B_  2
#define S_  4096
#define D_  512
#define H_  8
#define HD_ 64
#define BS_ (B_*S_)

// Scratch in head-split layout [B,H,S,HD] (16 MB each; static device arrays
// are allowed — no runtime allocation).
__device__ float g_q[B_*H_*S_*HD_];
__device__ float g_k[B_*H_*S_*HD_];
__device__ float g_v[B_*H_*S_*HD_];

// ---------------------------------------------------------------------------
// Fused QKV projection: y = x @ W^T + b, written directly into [B,H,S,HD].
// Tiles: BM=64, BN=64, BK=32. 256 threads (16x16), 4x4 micro-tile per thread.
// blockIdx.z selects {Wq,Wk,Wv}.
// ---------------------------------------------------------------------------
__global__ void __launch_bounds__(256) qkv_gemm(
    const float* __restrict__ x,
    const float* __restrict__ Wq, const float* __restrict__ bq,
    const float* __restrict__ Wk, const float* __restrict__ bk,
    const float* __restrict__ Wv, const float* __restrict__ bv)
{
    __shared__ float As[32][65];
    __shared__ float Bs[32][65];

    const int z = blockIdx.z;
    const float* W    = (z == 0) ? Wq : ((z == 1) ? Wk : Wv);
    const float* bias = (z == 0) ? bq : ((z == 1) ? bk : bv);
    float* dst        = (z == 0) ? g_q : ((z == 1) ? g_k : g_v);

    const int m0 = blockIdx.y * 64;
    const int n0 = blockIdx.x * 64;
    const int tx = threadIdx.x, ty = threadIdx.y;
    const int t  = ty * 16 + tx;

    float acc[4][4] = {};

    for (int k0 = 0; k0 < D_; k0 += 32) {
        // Load A (x) and B (W) 64x32 tiles, float4 along k, transposed store.
        #pragma unroll
        for (int i = 0; i < 2; i++) {
            int f  = t + i * 256;        // 0..511
            int m  = f >> 3;             // 8 float4 per row
            int kq = (f & 7) * 4;
            float4 a4 = *(const float4*)(x + (size_t)(m0 + m) * D_ + k0 + kq);
            As[kq + 0][m] = a4.x; As[kq + 1][m] = a4.y;
            As[kq + 2][m] = a4.z; As[kq + 3][m] = a4.w;
            float4 w4 = *(const float4*)(W + (size_t)(n0 + m) * D_ + k0 + kq);
            Bs[kq + 0][m] = w4.x; Bs[kq + 1][m] = w4.y;
            Bs[kq + 2][m] = w4.z; Bs[kq + 3][m] = w4.w;
        }
        __syncthreads();

        #pragma unroll
        for (int k = 0; k < 32; k++) {
            float a[4], bb[4];
            #pragma unroll
            for (int i = 0; i < 4; i++) a[i]  = As[k][4 * ty + i];
            #pragma unroll
            for (int j = 0; j < 4; j++) bb[j] = Bs[k][4 * tx + j];
            #pragma unroll
            for (int i = 0; i < 4; i++)
                #pragma unroll
                for (int j = 0; j < 4; j++)
                    acc[i][j] = fmaf(a[i], bb[j], acc[i][j]);
        }
        __syncthreads();
    }

    // Epilogue: add bias, scatter to [B,H,S,HD].
    #pragma unroll
    for (int i = 0; i < 4; i++) {
        int row = m0 + 4 * ty + i;
        int b   = row >> 12;             // / 4096
        int s   = row & 4095;
        #pragma unroll
        for (int j = 0; j < 4; j++) {
            int n  = n0 + 4 * tx + j;
            int h  = n >> 6;
            int hd = n & 63;
            dst[(((size_t)b * H_ + h) * S_ + s) * HD_ + hd] = acc[i][j] + bias[n];
        }
    }
}

// ---------------------------------------------------------------------------
// Causal flash attention. Q-tile = 64 rows, K-tile = 32 cols. 256 threads
// (16x16). S-phase: 4 rows x 2 cols per thread. PV-phase: 4x4 per thread.
// Static shared memory only (41.7 KB) — no cudaFuncSetAttribute needed.
// Row stats replicated across the 16-thread row group via shfl_xor
// (offsets 1..8 stay within 16-lane halves).
// ---------------------------------------------------------------------------
__global__ void __launch_bounds__(256) attn_kernel(float* __restrict__ out)
{
    __shared__ float Qs[64][65];
    __shared__ float Ks[32][65];
    __shared__ float Vs[32][65];
    __shared__ float Ps[64][33];

    // Heavy tiles (large qt) first to reduce wave-tail imbalance.
    const int qt = (int)gridDim.x - 1 - (int)blockIdx.x;
    const int bh = blockIdx.y;       // b*H + h
    const int tx = threadIdx.x, ty = threadIdx.y;
    const int t  = ty * 16 + tx;
    const float scale = rsqrtf((float)D_);   // faithful: 1/sqrt(D), not head_dim

    const float* Qg = g_q + (size_t)bh * S_ * HD_;
    const float* Kg = g_k + (size_t)bh * S_ * HD_;
    const float* Vg = g_v + (size_t)bh * S_ * HD_;

    const int q0 = qt * 64;

    // Load Q tile (pre-scaled).
    for (int i = t; i < 64 * 64; i += 256) {
        int r = i >> 6, d = i & 63;
        Qs[r][d] = Qg[(size_t)(q0 + r) * HD_ + d] * scale;
    }

    float acc[4][4] = {};
    float m_i[4], l_i[4];
    #pragma unroll
    for (int i = 0; i < 4; i++) { m_i[i] = -INFINITY; l_i[i] = 0.f; }

    __syncthreads();

    const int nkt = 2 * (qt + 1);            // k-tiles of 32, up to diagonal
    for (int kt = 0; kt < nkt; kt++) {
        const int k0 = kt * 32;
        for (int i = t; i < 32 * 64; i += 256) {
            int r = i >> 6, d = i & 63;
            Ks[r][d] = Kg[(size_t)(k0 + r) * HD_ + d];
            Vs[r][d] = Vg[(size_t)(k0 + r) * HD_ + d];
        }
        __syncthreads();

        // S = Q K^T  (4 rows x 2 cols per thread)
        float s[4][2] = {};
        #pragma unroll 8
        for (int d = 0; d < 64; d++) {
            float a[4], bb[2];
            #pragma unroll
            for (int i = 0; i < 4; i++) a[i]  = Qs[4 * ty + i][d];
            #pragma unroll
            for (int j = 0; j < 2; j++) bb[j] = Ks[2 * tx + j][d];
            #pragma unroll
            for (int i = 0; i < 4; i++)
                #pragma unroll
                for (int j = 0; j < 2; j++)
                    s[i][j] = fmaf(a[i], bb[j], s[i][j]);
        }

        // Causal mask: needed only for tiles overlapping the diagonal band
        // (k0 + 31 > q0  <=>  last two k-tiles of this q-tile).
        if (k0 + 31 > q0) {
            #pragma unroll
            for (int i = 0; i < 4; i++)
                #pragma unroll
                for (int j = 0; j < 2; j++)
                    if (k0 + 2 * tx + j > q0 + 4 * ty + i) s[i][j] = -INFINITY;
        }

        // Row max across the 16-thread row group.
        float mnew[4];
        #pragma unroll
        for (int i = 0; i < 4; i++) {
            float mx = fmaxf(s[i][0], s[i][1]);
            #pragma unroll
            for (int off = 1; off < 16; off <<= 1)
                mx = fmaxf(mx, __shfl_xor_sync(0xffffffffu, mx, off));
            mnew[i] = fmaxf(m_i[i], mx);
        }

        // p = exp(s - m), row sums.
        float rs[4];
        #pragma unroll
        for (int i = 0; i < 4; i++) {
            float sum = 0.f;
            #pragma unroll
            for (int j = 0; j < 2; j++) {
                float p = __expf(s[i][j] - mnew[i]);
                s[i][j] = p;
                sum += p;
            }
            #pragma unroll
            for (int off = 1; off < 16; off <<= 1)
                sum += __shfl_xor_sync(0xffffffffu, sum, off);
            rs[i] = sum;
        }

        // Rescale running state. (__expf(-inf)=0 covers the first tile;
        // fully-masked rows only occur on kt>=1 where m_i is finite.)
        #pragma unroll
        for (int i = 0; i < 4; i++) {
            float corr = __expf(m_i[i] - mnew[i]);
            l_i[i] = l_i[i] * corr + rs[i];
            m_i[i] = mnew[i];
            #pragma unroll
            for (int j = 0; j < 4; j++) acc[i][j] *= corr;
        }

        // Stage P to shared for the PV GEMM.
        #pragma unroll
        for (int i = 0; i < 4; i++)
            #pragma unroll
            for (int j = 0; j < 2; j++)
                Ps[4 * ty + i][2 * tx + j] = s[i][j];
        __syncthreads();

        // acc += P V   (P: 64x32, V: 32x64 -> acc 4x4 per thread)
        #pragma unroll 8
        for (int jj = 0; jj < 32; jj++) {
            float p[4], vv[4];
            #pragma unroll
            for (int i = 0; i < 4; i++) p[i]  = Ps[4 * ty + i][jj];
            #pragma unroll
            for (int j = 0; j < 4; j++) vv[j] = Vs[jj][4 * tx + j];
            #pragma unroll
            for (int i = 0; i < 4; i++)
                #pragma unroll
                for (int j = 0; j < 4; j++)
                    acc[i][j] = fmaf(p[i], vv[j], acc[i][j]);
        }
        __syncthreads();
    }

    // Epilogue: normalize, write [B,S,D] with D index = h*64 + hd.
    const int b = bh >> 3;
    const int h = bh & 7;
    #pragma unroll
    for (int i = 0; i < 4; i++) {
        int srow  = q0 + 4 * ty + i;
        float inv = 1.f / l_i[i];
        #pragma unroll
        for (int j = 0; j < 4; j++) {
            out[((size_t)(b * S_ + srow)) * D_ + h * HD_ + 4 * tx + j] =
                acc[i][j] * inv;
        }
    }
}

// ---------------------------------------------------------------------------
extern "C" void kernel_launch(void* const* d_in, const int* in_sizes, int n_in,
                              void* d_out, int out_size)
{
    const float* x  = (const float*)d_in[0];
    const float* Wq = (const float*)d_in[1];
    const float* bq = (const float*)d_in[2];
    const float* Wk = (const float*)d_in[3];
    const float* bk = (const float*)d_in[4];
    const float* Wv = (const float*)d_in[5];
    const float* bv = (const float*)d_in[6];
    float* out = (float*)d_out;

    dim3 blk(16, 16);
    dim3 ggrid(D_ / 64, BS_ / 64, 3);
    qkv_gemm<<<ggrid, blk>>>(x, Wq, bq, Wk, bk, Wv, bv);

    attn_kernel<<<dim3(S_ / 64, B_ * H_), blk>>>(out);
}